// round 1
// baseline (speedup 1.0000x reference)
#include <cuda_runtime.h>
#include <math.h>

#define NN 100000
#define DD 128
#define EE 3200000

// ---------------- static device scratch (no allocations allowed) ----------------
__device__ float g_bufA[NN * DD];
__device__ float g_bufB[NN * DD];
__device__ int   g_cnt[NN];
__device__ int   g_cursor[NN];
__device__ int   g_rowptr[3][NN + 1];
__device__ int   g_ccol[3][EE];
__device__ float g_cval[3][EE];

// ---------------- CSR build ----------------
__global__ void hist_kernel(const int* __restrict__ rows, int* __restrict__ cnt) {
    int i = blockIdx.x * blockDim.x + threadIdx.x;
    if (i < EE) atomicAdd(&cnt[rows[i]], 1);
}

// single-block exclusive scan over NN counters; writes rowptr + cursor, zeroes cnt
__global__ void scan_kernel(int* __restrict__ cnt, int* __restrict__ rowptr,
                            int* __restrict__ cursor) {
    __shared__ int sums[1024];
    const int t = threadIdx.x;
    const int CH = (NN + 1023) / 1024;
    const int base = t * CH;
    int s = 0;
    for (int j = 0; j < CH; j++) {
        int i = base + j;
        if (i < NN) s += cnt[i];
    }
    sums[t] = s;
    __syncthreads();
    for (int off = 1; off < 1024; off <<= 1) {
        int v = 0;
        if (t >= off) v = sums[t - off];
        __syncthreads();
        if (t >= off) sums[t] += v;
        __syncthreads();
    }
    int prefix = (t == 0) ? 0 : sums[t - 1];
    for (int j = 0; j < CH; j++) {
        int i = base + j;
        if (i < NN) {
            int c = cnt[i];
            cnt[i] = 0;              // reset for next matrix / next replay
            rowptr[i] = prefix;
            cursor[i] = prefix;
            prefix += c;
        }
    }
    if (t == 1023) rowptr[NN] = prefix;
}

__global__ void scatter_kernel(const int* __restrict__ rows, const int* __restrict__ cols,
                               const float* __restrict__ vals, int* __restrict__ cursor,
                               int* __restrict__ ccol, float* __restrict__ cval) {
    int i = blockIdx.x * blockDim.x + threadIdx.x;
    if (i < EE) {
        int r = rows[i];
        int p = atomicAdd(&cursor[r], 1);
        ccol[p] = cols[i];
        cval[p] = vals[i];
    }
}

// ---------------- SpMM: one warp per output row, float4 per lane ----------------
// mode: 0 = write y only; 1 = write y and y2; 2 = write y and y2 += result
__global__ void spmm_kernel(const int* __restrict__ rowptr, const int* __restrict__ ccol,
                            const float* __restrict__ cval, const float* __restrict__ x,
                            float* __restrict__ y, float* __restrict__ y2,
                            int relu, int mode) {
    int gwarp = (blockIdx.x * blockDim.x + threadIdx.x) >> 5;
    int lane  = threadIdx.x & 31;
    if (gwarp >= NN) return;
    int beg = rowptr[gwarp];
    int end = rowptr[gwarp + 1];
    const float4* x4 = (const float4*)x;
    float4 acc = make_float4(0.f, 0.f, 0.f, 0.f);
    int e = beg;
    for (; e + 1 < end; e += 2) {
        int   c0 = __ldg(&ccol[e]);
        int   c1 = __ldg(&ccol[e + 1]);
        float v0 = __ldg(&cval[e]);
        float v1 = __ldg(&cval[e + 1]);
        float4 a = __ldg(&x4[(size_t)c0 * 32 + lane]);
        float4 b = __ldg(&x4[(size_t)c1 * 32 + lane]);
        acc.x += v0 * a.x + v1 * b.x;
        acc.y += v0 * a.y + v1 * b.y;
        acc.z += v0 * a.z + v1 * b.z;
        acc.w += v0 * a.w + v1 * b.w;
    }
    if (e < end) {
        int   c0 = __ldg(&ccol[e]);
        float v0 = __ldg(&cval[e]);
        float4 a = __ldg(&x4[(size_t)c0 * 32 + lane]);
        acc.x += v0 * a.x; acc.y += v0 * a.y; acc.z += v0 * a.z; acc.w += v0 * a.w;
    }
    if (relu) {
        acc.x = fmaxf(acc.x, 0.f); acc.y = fmaxf(acc.y, 0.f);
        acc.z = fmaxf(acc.z, 0.f); acc.w = fmaxf(acc.w, 0.f);
    }
    size_t oi = (size_t)gwarp * 32 + lane;
    ((float4*)y)[oi] = acc;
    if (mode == 1) {
        ((float4*)y2)[oi] = acc;
    } else if (mode == 2) {
        float4 o = ((float4*)y2)[oi];
        o.x += acc.x; o.y += acc.y; o.z += acc.z; o.w += acc.w;
        ((float4*)y2)[oi] = o;
    }
}

// ---------------- Linear: Y = X @ W (+ b), warp handles 8 rows ----------------
// block = 256 threads = 8 warps => 64 rows per block. W + row tile staged in smem.
__global__ void linear_kernel(const float* __restrict__ X, const float* __restrict__ W,
                              const float* __restrict__ bias, float* __restrict__ Y) {
    extern __shared__ float sm[];
    float* Ws = sm;                   // 128*128 floats
    float* Xs = sm + DD * DD;         // 64 rows * 128 floats
    __shared__ float bs[DD];

    const float4* W4 = (const float4*)W;
    float4* Ws4 = (float4*)Ws;
    for (int i = threadIdx.x; i < DD * DD / 4; i += blockDim.x) Ws4[i] = W4[i];
    if (threadIdx.x < DD) bs[threadIdx.x] = bias ? bias[threadIdx.x] : 0.f;

    const int rowBase = blockIdx.x * 64;
    const float4* X4 = (const float4*)X;
    float4* Xs4 = (float4*)Xs;
    for (int i = threadIdx.x; i < 64 * 32; i += blockDim.x) {
        int r = rowBase + (i >> 5);
        Xs4[i] = (r < NN) ? __ldg(&X4[(size_t)r * 32 + (i & 31)])
                          : make_float4(0.f, 0.f, 0.f, 0.f);
    }
    __syncthreads();

    const int warp = threadIdx.x >> 5;
    const int lane = threadIdx.x & 31;
    float4 acc[8];
#pragma unroll
    for (int r = 0; r < 8; r++) acc[r] = make_float4(0.f, 0.f, 0.f, 0.f);

    const float* xrow = Xs + warp * 8 * DD;
#pragma unroll 2
    for (int k = 0; k < DD; k++) {
        float4 wv = *(const float4*)(Ws + k * DD + lane * 4);
#pragma unroll
        for (int r = 0; r < 8; r++) {
            float xk = xrow[r * DD + k];
            acc[r].x += xk * wv.x;
            acc[r].y += xk * wv.y;
            acc[r].z += xk * wv.z;
            acc[r].w += xk * wv.w;
        }
    }
    float4 bv = *(const float4*)(bs + lane * 4);
    float4* Y4 = (float4*)Y;
#pragma unroll
    for (int r = 0; r < 8; r++) {
        int row = rowBase + warp * 8 + r;
        if (row < NN) {
            float4 o = acc[r];
            o.x += bv.x; o.y += bv.y; o.z += bv.z; o.w += bv.w;
            Y4[(size_t)row * 32 + lane] = o;
        }
    }
}

// ---------------- Gated fusion: warp handles 4 nodes, both views ----------------
__global__ void fusion_kernel(const float* __restrict__ x, const float* __restrict__ W1,
                              const float* __restrict__ b1, const float* __restrict__ w2,
                              const float* __restrict__ b2, float* __restrict__ fused) {
    extern __shared__ float sm[];
    float* Ws = sm;                 // 128*128
    float* Xs = sm + DD * DD;       // 32 nodes * 2 views * 128
    __shared__ float b1s[DD];
    __shared__ float w2s[DD];

    const float4* W4 = (const float4*)W1;
    float4* Ws4 = (float4*)Ws;
    for (int i = threadIdx.x; i < DD * DD / 4; i += blockDim.x) Ws4[i] = W4[i];
    if (threadIdx.x < DD) {
        b1s[threadIdx.x] = b1[threadIdx.x];
        w2s[threadIdx.x] = w2[threadIdx.x];
    }
    const float b2v = b2[0];

    const int nodeBase = blockIdx.x * 32;
    const float4* x4 = (const float4*)x;
    float4* Xs4 = (float4*)Xs;
    // layout: ((node*2 + v)*32 + q) float4s
    for (int i = threadIdx.x; i < 32 * 2 * 32; i += blockDim.x) {
        int node = i >> 6;
        int v    = (i >> 5) & 1;
        int q    = i & 31;
        int gn   = nodeBase + node;
        Xs4[i] = (gn < NN) ? __ldg(&x4[((size_t)v * NN + gn) * 32 + q])
                           : make_float4(0.f, 0.f, 0.f, 0.f);
    }
    __syncthreads();

    const int warp = threadIdx.x >> 5;
    const int lane = threadIdx.x & 31;
    const int n0 = warp * 4;

    float sc[2][4];
#pragma unroll
    for (int v = 0; v < 2; v++) {
        float4 acc[4];
#pragma unroll
        for (int r = 0; r < 4; r++) acc[r] = make_float4(0.f, 0.f, 0.f, 0.f);
#pragma unroll 2
        for (int k = 0; k < DD; k++) {
            float4 wv = *(const float4*)(Ws + k * DD + lane * 4);
#pragma unroll
            for (int r = 0; r < 4; r++) {
                float xk = Xs[((n0 + r) * 2 + v) * DD + k];
                acc[r].x += xk * wv.x;
                acc[r].y += xk * wv.y;
                acc[r].z += xk * wv.z;
                acc[r].w += xk * wv.w;
            }
        }
#pragma unroll
        for (int r = 0; r < 4; r++) {
            float h0 = tanhf(acc[r].x + b1s[lane * 4 + 0]);
            float h1 = tanhf(acc[r].y + b1s[lane * 4 + 1]);
            float h2 = tanhf(acc[r].z + b1s[lane * 4 + 2]);
            float h3 = tanhf(acc[r].w + b1s[lane * 4 + 3]);
            float p = h0 * w2s[lane * 4 + 0] + h1 * w2s[lane * 4 + 1] +
                      h2 * w2s[lane * 4 + 2] + h3 * w2s[lane * 4 + 3];
#pragma unroll
            for (int off = 16; off > 0; off >>= 1)
                p += __shfl_xor_sync(0xffffffffu, p, off);
            sc[v][r] = p + b2v;
        }
    }

    float4* out4 = (float4*)fused;
#pragma unroll
    for (int r = 0; r < 4; r++) {
        int node = nodeBase + n0 + r;
        if (node >= NN) continue;
        float m  = fmaxf(sc[0][r], sc[1][r]);
        float e0 = expf(sc[0][r] - m);
        float e1 = expf(sc[1][r] - m);
        float inv = 1.f / (e0 + e1);
        float s0 = e0 * inv, s1 = e1 * inv;
        float4 a = Xs4[((n0 + r) * 2 + 0) * 32 + lane];
        float4 b = Xs4[((n0 + r) * 2 + 1) * 32 + lane];
        float4 o;
        o.x = s0 * a.x + s1 * b.x;
        o.y = s0 * a.y + s1 * b.y;
        o.z = s0 * a.z + s1 * b.z;
        o.w = s0 * a.w + s1 * b.w;
        out4[(size_t)node * 32 + lane] = o;
    }
}

// ---------------- host ----------------
extern "C" void kernel_launch(void* const* d_in, const int* in_sizes, int n_in,
                              void* d_out, int out_size) {
    const float* x    = (const float*)d_in[0];
    const float* fw1  = (const float*)d_in[1];
    const float* fb1  = (const float*)d_in[2];
    const float* fw2  = (const float*)d_in[3];
    const float* fb2  = (const float*)d_in[4];
    const float* hgw  = (const float*)d_in[5];
    const float* lgw  = (const float*)d_in[6];
    const float* lgb  = (const float*)d_in[7];
    const float* c1v  = (const float*)d_in[8];
    const float* c2v  = (const float*)d_in[9];
    const float* lgv  = (const float*)d_in[10];
    const int* c1r = (const int*)d_in[11];
    const int* c1c = (const int*)d_in[12];
    const int* c2r = (const int*)d_in[13];
    const int* c2c = (const int*)d_in[14];
    const int* lgr = (const int*)d_in[15];
    const int* lgc = (const int*)d_in[16];
    float* out = (float*)d_out;   // [2N, D]

    float *bufA, *bufB, *cvalBase;
    int *cnt, *cursor, *rowptrBase, *ccolBase;
    cudaGetSymbolAddress((void**)&bufA, g_bufA);
    cudaGetSymbolAddress((void**)&bufB, g_bufB);
    cudaGetSymbolAddress((void**)&cnt, g_cnt);
    cudaGetSymbolAddress((void**)&cursor, g_cursor);
    cudaGetSymbolAddress((void**)&rowptrBase, g_rowptr);
    cudaGetSymbolAddress((void**)&ccolBase, g_ccol);
    cudaGetSymbolAddress((void**)&cvalBase, g_cval);

    int* rowptr[3];
    int* ccol[3];
    float* cval[3];
    for (int m = 0; m < 3; m++) {
        rowptr[m] = rowptrBase + (size_t)m * (NN + 1);
        ccol[m]   = ccolBase + (size_t)m * EE;
        cval[m]   = cvalBase + (size_t)m * EE;
    }

    const size_t smemBig = (size_t)(DD * DD + 64 * DD) * sizeof(float);   // 96 KB
    cudaFuncSetAttribute(linear_kernel, cudaFuncAttributeMaxDynamicSharedMemorySize, (int)smemBig);
    cudaFuncSetAttribute(fusion_kernel, cudaFuncAttributeMaxDynamicSharedMemorySize, (int)smemBig);

    const int EB = (EE + 255) / 256;           // 12500
    const int SPB = (NN * 32 + 255) / 256;     // warp-per-row grid
    const int LB = (NN + 63) / 64;             // linear grid
    const int FB = (NN + 31) / 32;             // fusion grid

    // ---- CSR builds ----
    const int* rr[3] = { c1r, c2r, lgr };
    const int* cc[3] = { c1c, c2c, lgc };
    const float* vv[3] = { c1v, c2v, lgv };
    for (int m = 0; m < 3; m++) {
        hist_kernel<<<EB, 256>>>(rr[m], cnt);
        scan_kernel<<<1, 1024>>>(cnt, rowptr[m], cursor);
        scatter_kernel<<<EB, 256>>>(rr[m], cc[m], vv[m], cursor, ccol[m], cval[m]);
    }

    // ---- gated fusion -> bufA ----
    fusion_kernel<<<FB, 256, smemBig>>>(x, fw1, fb1, fw2, fb2, bufA);

    // ---- HypergraphConv ----
    linear_kernel<<<LB, 256, smemBig>>>(bufA, hgw + 0 * DD * DD, nullptr, bufB);
    spmm_kernel<<<SPB, 256>>>(rowptr[0], ccol[0], cval[0], bufB, bufA, nullptr, 1, 0);
    linear_kernel<<<LB, 256, smemBig>>>(bufA, hgw + 1 * DD * DD, nullptr, bufB);
    spmm_kernel<<<SPB, 256>>>(rowptr[0], ccol[0], cval[0], bufB, bufA, nullptr, 1, 0);
    linear_kernel<<<LB, 256, smemBig>>>(bufA, hgw + 2 * DD * DD, nullptr, bufB);
    // h -> first half of output
    spmm_kernel<<<SPB, 256>>>(rowptr[0], ccol[0], cval[0], bufB, out, nullptr, 1, 0);
    // y = relu(spmm(coef2, h)); cur = y (bufB), acc = y (second half of output)
    spmm_kernel<<<SPB, 256>>>(rowptr[1], ccol[1], cval[1], out, bufB, out + (size_t)NN * DD, 1, 1);

    // ---- LineConv ----
    linear_kernel<<<LB, 256, smemBig>>>(bufB, lgw + 0 * DD * DD, lgb + 0 * DD, bufA);
    spmm_kernel<<<SPB, 256>>>(rowptr[2], ccol[2], cval[2], bufA, bufB, out + (size_t)NN * DD, 0, 2);
    linear_kernel<<<LB, 256, smemBig>>>(bufB, lgw + 1 * DD * DD, lgb + 1 * DD, bufA);
    spmm_kernel<<<SPB, 256>>>(rowptr[2], ccol[2], cval[2], bufA, bufB, out + (size_t)NN * DD, 0, 2);
}

// round 2
// speedup vs baseline: 1.0300x; 1.0300x over previous
#include <cuda_runtime.h>
#include <cuda_fp16.h>
#include <math.h>

#define NN 100000
#define DD 128
#define EE 3200000

// ---------------- static device scratch (no allocations allowed) ----------------
__device__ float  g_bufA[NN * DD];
__device__ float  g_bufB[NN * DD];
__device__ __half2 g_h16a[NN * (DD / 2)];
__device__ __half2 g_h16b[NN * (DD / 2)];
__device__ int    g_cnt[NN];
__device__ int    g_cursor[NN];
__device__ int    g_rowptr[3][NN + 1];
__device__ int2   g_epack[3][EE];     // (col, val-bits) packed

// ---------------- CSR build ----------------
__global__ void hist_kernel(const int* __restrict__ rows, int* __restrict__ cnt) {
    int i = blockIdx.x * blockDim.x + threadIdx.x;
    int base = i * 4;
    if (base + 3 < EE) {
        int4 r = __ldg((const int4*)(rows + base));
        atomicAdd(&cnt[r.x], 1);
        atomicAdd(&cnt[r.y], 1);
        atomicAdd(&cnt[r.z], 1);
        atomicAdd(&cnt[r.w], 1);
    } else {
        for (int j = base; j < EE; j++) atomicAdd(&cnt[rows[j]], 1);
    }
}

// single-block exclusive scan over NN counters; writes rowptr + cursor, zeroes cnt
__global__ void scan_kernel(int* __restrict__ cnt, int* __restrict__ rowptr,
                            int* __restrict__ cursor) {
    __shared__ int sums[1024];
    const int t = threadIdx.x;
    const int CH = (NN + 1023) / 1024;
    const int base = t * CH;
    int s = 0;
    for (int j = 0; j < CH; j++) {
        int i = base + j;
        if (i < NN) s += cnt[i];
    }
    sums[t] = s;
    __syncthreads();
    for (int off = 1; off < 1024; off <<= 1) {
        int v = 0;
        if (t >= off) v = sums[t - off];
        __syncthreads();
        if (t >= off) sums[t] += v;
        __syncthreads();
    }
    int prefix = (t == 0) ? 0 : sums[t - 1];
    for (int j = 0; j < CH; j++) {
        int i = base + j;
        if (i < NN) {
            int c = cnt[i];
            cnt[i] = 0;              // reset for next matrix / next replay
            rowptr[i] = prefix;
            cursor[i] = prefix;
            prefix += c;
        }
    }
    if (t == 1023) rowptr[NN] = prefix;
}

__global__ void scatter_kernel(const int* __restrict__ rows, const int* __restrict__ cols,
                               const float* __restrict__ vals, int* __restrict__ cursor,
                               int2* __restrict__ epack) {
    int i = blockIdx.x * blockDim.x + threadIdx.x;
    if (i < EE) {
        int r = rows[i];
        int p = atomicAdd(&cursor[r], 1);
        epack[p] = make_int2(cols[i], __float_as_int(vals[i]));
    }
}

// ---------------- SpMM: warp per row, fp16 gather table, fp32 accumulate ----------
// x row = 32 uint2 (each lane: 4 halves).  Outputs optional.
__global__ void spmm_kernel(const int* __restrict__ rowptr, const int2* __restrict__ epack,
                            const __half2* __restrict__ x,
                            float* __restrict__ yF, __half2* __restrict__ yH,
                            float* __restrict__ acc, int relu, int accWrite) {
    int gwarp = (blockIdx.x * blockDim.x + threadIdx.x) >> 5;
    int lane  = threadIdx.x & 31;
    if (gwarp >= NN) return;
    int beg = rowptr[gwarp];
    int end = rowptr[gwarp + 1];
    const uint2* x2 = (const uint2*)x;

    float4 a0 = make_float4(0.f, 0.f, 0.f, 0.f);
    float4 a1 = make_float4(0.f, 0.f, 0.f, 0.f);
    int e = beg;
    for (; e + 1 < end; e += 2) {
        int2 p0 = __ldg(&epack[e]);
        int2 p1 = __ldg(&epack[e + 1]);
        float v0 = __int_as_float(p0.y);
        float v1 = __int_as_float(p1.y);
        uint2 r0 = __ldg(&x2[(size_t)p0.x * 32 + lane]);
        uint2 r1 = __ldg(&x2[(size_t)p1.x * 32 + lane]);
        float2 f00 = __half22float2(*(__half2*)&r0.x);
        float2 f01 = __half22float2(*(__half2*)&r0.y);
        float2 f10 = __half22float2(*(__half2*)&r1.x);
        float2 f11 = __half22float2(*(__half2*)&r1.y);
        a0.x += v0 * f00.x; a0.y += v0 * f00.y; a0.z += v0 * f01.x; a0.w += v0 * f01.y;
        a1.x += v1 * f10.x; a1.y += v1 * f10.y; a1.z += v1 * f11.x; a1.w += v1 * f11.y;
    }
    if (e < end) {
        int2 p0 = __ldg(&epack[e]);
        float v0 = __int_as_float(p0.y);
        uint2 r0 = __ldg(&x2[(size_t)p0.x * 32 + lane]);
        float2 f00 = __half22float2(*(__half2*)&r0.x);
        float2 f01 = __half22float2(*(__half2*)&r0.y);
        a0.x += v0 * f00.x; a0.y += v0 * f00.y; a0.z += v0 * f01.x; a0.w += v0 * f01.y;
    }
    float4 r;
    r.x = a0.x + a1.x; r.y = a0.y + a1.y; r.z = a0.z + a1.z; r.w = a0.w + a1.w;
    if (relu) {
        r.x = fmaxf(r.x, 0.f); r.y = fmaxf(r.y, 0.f);
        r.z = fmaxf(r.z, 0.f); r.w = fmaxf(r.w, 0.f);
    }
    size_t oi = (size_t)gwarp * 32 + lane;
    if (yF) ((float4*)yF)[oi] = r;
    if (yH) {
        uint2 hv;
        __half2 h0 = __floats2half2_rn(r.x, r.y);
        __half2 h1 = __floats2half2_rn(r.z, r.w);
        hv.x = *(unsigned*)&h0;
        hv.y = *(unsigned*)&h1;
        ((uint2*)yH)[oi] = hv;
    }
    if (acc) {
        if (accWrite) {
            ((float4*)acc)[oi] = r;
        } else {
            float4 o = ((float4*)acc)[oi];
            o.x += r.x; o.y += r.y; o.z += r.z; o.w += r.w;
            ((float4*)acc)[oi] = o;
        }
    }
}

// ---------------- Linear: Yh = half(X @ W + b), warp handles 8 rows ----------------
__global__ void linear_kernel(const float* __restrict__ X, const float* __restrict__ W,
                              const float* __restrict__ bias, __half2* __restrict__ Yh) {
    extern __shared__ float sm[];
    float* Ws = sm;                   // 128*128 floats
    float* Xs = sm + DD * DD;         // 64 rows * 128 floats
    __shared__ float bs[DD];

    const float4* W4 = (const float4*)W;
    float4* Ws4 = (float4*)Ws;
    for (int i = threadIdx.x; i < DD * DD / 4; i += blockDim.x) Ws4[i] = W4[i];
    if (threadIdx.x < DD) bs[threadIdx.x] = bias ? bias[threadIdx.x] : 0.f;

    const int rowBase = blockIdx.x * 64;
    const float4* X4 = (const float4*)X;
    float4* Xs4 = (float4*)Xs;
    for (int i = threadIdx.x; i < 64 * 32; i += blockDim.x) {
        int r = rowBase + (i >> 5);
        Xs4[i] = (r < NN) ? __ldg(&X4[(size_t)r * 32 + (i & 31)])
                          : make_float4(0.f, 0.f, 0.f, 0.f);
    }
    __syncthreads();

    const int warp = threadIdx.x >> 5;
    const int lane = threadIdx.x & 31;
    float4 acc[8];
#pragma unroll
    for (int r = 0; r < 8; r++) acc[r] = make_float4(0.f, 0.f, 0.f, 0.f);

    const float* xrow = Xs + warp * 8 * DD;
#pragma unroll 2
    for (int k = 0; k < DD; k++) {
        float4 wv = *(const float4*)(Ws + k * DD + lane * 4);
#pragma unroll
        for (int r = 0; r < 8; r++) {
            float xk = xrow[r * DD + k];
            acc[r].x += xk * wv.x;
            acc[r].y += xk * wv.y;
            acc[r].z += xk * wv.z;
            acc[r].w += xk * wv.w;
        }
    }
    float4 bv = *(const float4*)(bs + lane * 4);
#pragma unroll
    for (int r = 0; r < 8; r++) {
        int row = rowBase + warp * 8 + r;
        if (row < NN) {
            float4 o = acc[r];
            o.x += bv.x; o.y += bv.y; o.z += bv.z; o.w += bv.w;
            __half2 h0 = __floats2half2_rn(o.x, o.y);
            __half2 h1 = __floats2half2_rn(o.z, o.w);
            uint2 hv;
            hv.x = *(unsigned*)&h0;
            hv.y = *(unsigned*)&h1;
            ((uint2*)Yh)[(size_t)row * 32 + lane] = hv;
        }
    }
}

// ---------------- Gated fusion: warp handles 4 nodes, both views ----------------
__global__ void fusion_kernel(const float* __restrict__ x, const float* __restrict__ W1,
                              const float* __restrict__ b1, const float* __restrict__ w2,
                              const float* __restrict__ b2, float* __restrict__ fused) {
    extern __shared__ float sm[];
    float* Ws = sm;                 // 128*128
    float* Xs = sm + DD * DD;       // 32 nodes * 2 views * 128
    __shared__ float b1s[DD];
    __shared__ float w2s[DD];

    const float4* W4 = (const float4*)W1;
    float4* Ws4 = (float4*)Ws;
    for (int i = threadIdx.x; i < DD * DD / 4; i += blockDim.x) Ws4[i] = W4[i];
    if (threadIdx.x < DD) {
        b1s[threadIdx.x] = b1[threadIdx.x];
        w2s[threadIdx.x] = w2[threadIdx.x];
    }
    const float b2v = b2[0];

    const int nodeBase = blockIdx.x * 32;
    const float4* x4 = (const float4*)x;
    float4* Xs4 = (float4*)Xs;
    for (int i = threadIdx.x; i < 32 * 2 * 32; i += blockDim.x) {
        int node = i >> 6;
        int v    = (i >> 5) & 1;
        int q    = i & 31;
        int gn   = nodeBase + node;
        Xs4[i] = (gn < NN) ? __ldg(&x4[((size_t)v * NN + gn) * 32 + q])
                           : make_float4(0.f, 0.f, 0.f, 0.f);
    }
    __syncthreads();

    const int warp = threadIdx.x >> 5;
    const int lane = threadIdx.x & 31;
    const int n0 = warp * 4;

    float sc[2][4];
#pragma unroll
    for (int v = 0; v < 2; v++) {
        float4 acc[4];
#pragma unroll
        for (int r = 0; r < 4; r++) acc[r] = make_float4(0.f, 0.f, 0.f, 0.f);
#pragma unroll 2
        for (int k = 0; k < DD; k++) {
            float4 wv = *(const float4*)(Ws + k * DD + lane * 4);
#pragma unroll
            for (int r = 0; r < 4; r++) {
                float xk = Xs[((n0 + r) * 2 + v) * DD + k];
                acc[r].x += xk * wv.x;
                acc[r].y += xk * wv.y;
                acc[r].z += xk * wv.z;
                acc[r].w += xk * wv.w;
            }
        }
#pragma unroll
        for (int r = 0; r < 4; r++) {
            float h0 = tanhf(acc[r].x + b1s[lane * 4 + 0]);
            float h1 = tanhf(acc[r].y + b1s[lane * 4 + 1]);
            float h2 = tanhf(acc[r].z + b1s[lane * 4 + 2]);
            float h3 = tanhf(acc[r].w + b1s[lane * 4 + 3]);
            float p = h0 * w2s[lane * 4 + 0] + h1 * w2s[lane * 4 + 1] +
                      h2 * w2s[lane * 4 + 2] + h3 * w2s[lane * 4 + 3];
#pragma unroll
            for (int off = 16; off > 0; off >>= 1)
                p += __shfl_xor_sync(0xffffffffu, p, off);
            sc[v][r] = p + b2v;
        }
    }

    float4* out4 = (float4*)fused;
#pragma unroll
    for (int r = 0; r < 4; r++) {
        int node = nodeBase + n0 + r;
        if (node >= NN) continue;
        float m  = fmaxf(sc[0][r], sc[1][r]);
        float e0 = expf(sc[0][r] - m);
        float e1 = expf(sc[1][r] - m);
        float inv = 1.f / (e0 + e1);
        float s0 = e0 * inv, s1 = e1 * inv;
        float4 a = Xs4[((n0 + r) * 2 + 0) * 32 + lane];
        float4 b = Xs4[((n0 + r) * 2 + 1) * 32 + lane];
        float4 o;
        o.x = s0 * a.x + s1 * b.x;
        o.y = s0 * a.y + s1 * b.y;
        o.z = s0 * a.z + s1 * b.z;
        o.w = s0 * a.w + s1 * b.w;
        out4[(size_t)node * 32 + lane] = o;
    }
}

// ---------------- host ----------------
extern "C" void kernel_launch(void* const* d_in, const int* in_sizes, int n_in,
                              void* d_out, int out_size) {
    const float* x    = (const float*)d_in[0];
    const float* fw1  = (const float*)d_in[1];
    const float* fb1  = (const float*)d_in[2];
    const float* fw2  = (const float*)d_in[3];
    const float* fb2  = (const float*)d_in[4];
    const float* hgw  = (const float*)d_in[5];
    const float* lgw  = (const float*)d_in[6];
    const float* lgb  = (const float*)d_in[7];
    const float* c1v  = (const float*)d_in[8];
    const float* c2v  = (const float*)d_in[9];
    const float* lgv  = (const float*)d_in[10];
    const int* c1r = (const int*)d_in[11];
    const int* c1c = (const int*)d_in[12];
    const int* c2r = (const int*)d_in[13];
    const int* c2c = (const int*)d_in[14];
    const int* lgr = (const int*)d_in[15];
    const int* lgc = (const int*)d_in[16];
    float* out = (float*)d_out;   // [2N, D]
    float* out2 = out + (size_t)NN * DD;

    float *bufA, *bufB;
    __half2 *h16a, *h16b;
    int *cnt, *cursor, *rowptrBase;
    int2 *epackBase;
    cudaGetSymbolAddress((void**)&bufA, g_bufA);
    cudaGetSymbolAddress((void**)&bufB, g_bufB);
    cudaGetSymbolAddress((void**)&h16a, g_h16a);
    cudaGetSymbolAddress((void**)&h16b, g_h16b);
    cudaGetSymbolAddress((void**)&cnt, g_cnt);
    cudaGetSymbolAddress((void**)&cursor, g_cursor);
    cudaGetSymbolAddress((void**)&rowptrBase, g_rowptr);
    cudaGetSymbolAddress((void**)&epackBase, g_epack);

    int* rowptr[3];
    int2* epack[3];
    for (int m = 0; m < 3; m++) {
        rowptr[m] = rowptrBase + (size_t)m * (NN + 1);
        epack[m]  = epackBase + (size_t)m * EE;
    }

    const size_t smemBig = (size_t)(DD * DD + 64 * DD) * sizeof(float);   // 96 KB
    cudaFuncSetAttribute(linear_kernel, cudaFuncAttributeMaxDynamicSharedMemorySize, (int)smemBig);
    cudaFuncSetAttribute(fusion_kernel, cudaFuncAttributeMaxDynamicSharedMemorySize, (int)smemBig);

    const int EB  = (EE + 255) / 256;            // scatter grid
    const int HB  = (EE / 4 + 255) / 256;        // hist grid (4 per thread)
    const int SPB = (NN * 32 + 255) / 256;       // warp-per-row grid
    const int LB  = (NN + 63) / 64;              // linear grid
    const int FB  = (NN + 31) / 32;              // fusion grid

    // ---- CSR builds ----
    const int* rr[3] = { c1r, c2r, lgr };
    const int* cc[3] = { c1c, c2c, lgc };
    const float* vv[3] = { c1v, c2v, lgv };
    for (int m = 0; m < 3; m++) {
        hist_kernel<<<HB, 256>>>(rr[m], cnt);
        scan_kernel<<<1, 1024>>>(cnt, rowptr[m], cursor);
        scatter_kernel<<<EB, 256>>>(rr[m], cc[m], vv[m], cursor, epack[m]);
    }

    // ---- gated fusion -> bufA (fp32) ----
    fusion_kernel<<<FB, 256, smemBig>>>(x, fw1, fb1, fw2, fb2, bufA);

    // ---- HypergraphConv ----
    linear_kernel<<<LB, 256, smemBig>>>(bufA, hgw + 0 * DD * DD, nullptr, h16a);
    spmm_kernel<<<SPB, 256>>>(rowptr[0], epack[0], h16a, bufB, nullptr, nullptr, 1, 0);
    linear_kernel<<<LB, 256, smemBig>>>(bufB, hgw + 1 * DD * DD, nullptr, h16a);
    spmm_kernel<<<SPB, 256>>>(rowptr[0], epack[0], h16a, bufB, nullptr, nullptr, 1, 0);
    linear_kernel<<<LB, 256, smemBig>>>(bufB, hgw + 2 * DD * DD, nullptr, h16a);
    // h -> first half of output (fp32) + fp16 shadow for the coef2 spmm
    spmm_kernel<<<SPB, 256>>>(rowptr[0], epack[0], h16a, out, h16b, nullptr, 1, 0);
    // y = relu(spmm(coef2, h)); y -> bufB (cur), acc init -> out2
    spmm_kernel<<<SPB, 256>>>(rowptr[1], epack[1], h16b, bufB, nullptr, out2, 1, 1);

    // ---- LineConv ----
    linear_kernel<<<LB, 256, smemBig>>>(bufB, lgw + 0 * DD * DD, lgb + 0 * DD, h16a);
    spmm_kernel<<<SPB, 256>>>(rowptr[2], epack[2], h16a, bufA, nullptr, out2, 0, 0);
    linear_kernel<<<LB, 256, smemBig>>>(bufA, lgw + 1 * DD * DD, lgb + 1 * DD, h16a);
    spmm_kernel<<<SPB, 256>>>(rowptr[2], epack[2], h16a, nullptr, nullptr, out2, 0, 0);
}

// round 5
// speedup vs baseline: 1.3057x; 1.2677x over previous
#include <cuda_runtime.h>
#include <cuda_fp16.h>
#include <math.h>
#include <stdint.h>

#define NN 100000
#define DD 128
#define EE 3200000
#define SCHUNK 256
#define SNB ((NN + SCHUNK - 1) / SCHUNK)   // 391
#define AST 136                            // smem row stride (halves), conflict-free ldmatrix

extern __shared__ char dynsm[];

// ---------------- static device scratch ----------------
__device__ __half2 g_h16a[NN * (DD / 2)];
__device__ __half2 g_h16b[NN * (DD / 2)];
__device__ int    g_cnt[3][NN];
__device__ int    g_cursor[3][NN];
__device__ int    g_rowptr[3][NN + 1];
__device__ int2   g_epack[3][EE];
__device__ int    g_bsum[3][SNB];
__device__ int    g_boff[3][SNB];
__device__ __half g_wt[5][DD * DD];        // transposed fp16 weights: Bt[n][k] = W[k][n]

__device__ __forceinline__ uint32_t smem_u32(const void* p) {
    uint32_t a;
    asm("{ .reg .u64 t; cvta.to.shared.u64 t, %1; cvt.u32.u64 %0, t; }" : "=r"(a) : "l"(p));
    return a;
}

// ---------------- weight prep: fp16 transpose ----------------
__global__ void wprep_kernel(const float* __restrict__ hgw, const float* __restrict__ lgw) {
    int m = blockIdx.y;
    const float* W = (m < 3) ? (hgw + (size_t)m * DD * DD) : (lgw + (size_t)(m - 3) * DD * DD);
    int i = blockIdx.x * blockDim.x + threadIdx.x;
    if (i >= DD * DD) return;
    int n = i >> 7, k = i & 127;
    g_wt[m][n * DD + k] = __float2half_rn(__ldg(&W[k * DD + n]));
}

// ---------------- MMA linear: Y = half(X @ W + b); tile 128x128x128 ----------------
// 256 threads = 8 warps as 4(M) x 2(N); warp tile 32x64.
__global__ void __launch_bounds__(256, 2) mma_linear_kernel(
    const uint4* __restrict__ X,      // fp16 [NN,128] row-major (16 uint4/row)
    const uint4* __restrict__ Bt,     // fp16 [128,128] = W^T row-major
    const float* __restrict__ bias,   // may be null
    __half2* __restrict__ Y)          // fp16 [NN,128]
{
    __half* sm = (__half*)dynsm;
    __half* sA = sm;                  // 128 * AST
    __half* sB = sm + 128 * AST;      // 128 * AST
    float* bs = (float*)(sm + 2 * 128 * AST);

    const int tid = threadIdx.x;
    const int lane = tid & 31;
    const int warp = tid >> 5;
    const int warpM = warp & 3;       // 0..3
    const int warpN = warp >> 2;      // 0..1
    const int rowBase = blockIdx.x * 128;

    for (int i = tid; i < 2048; i += 256) {
        int r = i >> 4, c = i & 15;
        int gr = rowBase + r;
        uint4 v = (gr < NN) ? __ldg(&X[(size_t)gr * 16 + c]) : make_uint4(0u, 0u, 0u, 0u);
        *(uint4*)&sA[r * AST + c * 8] = v;
    }
    for (int i = tid; i < 2048; i += 256) {
        int r = i >> 4, c = i & 15;
        *(uint4*)&sB[r * AST + c * 8] = __ldg(&Bt[i]);
    }
    if (tid < 128) bs[tid] = bias ? __ldg(&bias[tid]) : 0.f;
    __syncthreads();

    float acc[2][8][4];
#pragma unroll
    for (int mi = 0; mi < 2; mi++)
#pragma unroll
        for (int ni = 0; ni < 8; ni++)
#pragma unroll
            for (int q = 0; q < 4; q++) acc[mi][ni][q] = 0.f;

#pragma unroll
    for (int k0 = 0; k0 < 128; k0 += 16) {
        uint32_t a[2][4];
#pragma unroll
        for (int mi = 0; mi < 2; mi++) {
            int row = warpM * 32 + mi * 16 + (lane & 15);
            int col = k0 + ((lane >> 4) << 3);
            uint32_t addr = smem_u32(&sA[row * AST + col]);
            asm volatile("ldmatrix.sync.aligned.m8n8.x4.shared.b16 {%0,%1,%2,%3}, [%4];"
                         : "=r"(a[mi][0]), "=r"(a[mi][1]), "=r"(a[mi][2]), "=r"(a[mi][3])
                         : "r"(addr));
        }
        uint32_t b[8][2];
#pragma unroll
        for (int ni = 0; ni < 8; ni++) {
            int n = warpN * 64 + ni * 8 + (lane & 7);
            int col = k0 + (((lane >> 3) & 1) << 3);
            uint32_t addr = smem_u32(&sB[n * AST + col]);
            asm volatile("ldmatrix.sync.aligned.m8n8.x2.shared.b16 {%0,%1}, [%2];"
                         : "=r"(b[ni][0]), "=r"(b[ni][1]) : "r"(addr));
        }
#pragma unroll
        for (int mi = 0; mi < 2; mi++)
#pragma unroll
            for (int ni = 0; ni < 8; ni++) {
                asm volatile(
                    "mma.sync.aligned.m16n8k16.row.col.f32.f16.f16.f32 "
                    "{%0,%1,%2,%3}, {%4,%5,%6,%7}, {%8,%9}, {%0,%1,%2,%3};"
                    : "+f"(acc[mi][ni][0]), "+f"(acc[mi][ni][1]),
                      "+f"(acc[mi][ni][2]), "+f"(acc[mi][ni][3])
                    : "r"(a[mi][0]), "r"(a[mi][1]), "r"(a[mi][2]), "r"(a[mi][3]),
                      "r"(b[ni][0]), "r"(b[ni][1]));
            }
    }

    const int g = lane >> 2, t = lane & 3;
#pragma unroll
    for (int mi = 0; mi < 2; mi++) {
#pragma unroll
        for (int ni = 0; ni < 8; ni++) {
            int col = warpN * 64 + ni * 8 + t * 2;
            float b0 = bs[col], b1 = bs[col + 1];
            int r0 = rowBase + warpM * 32 + mi * 16 + g;
            int r1 = r0 + 8;
            if (r0 < NN)
                Y[(size_t)r0 * 64 + (col >> 1)] =
                    __floats2half2_rn(acc[mi][ni][0] + b0, acc[mi][ni][1] + b1);
            if (r1 < NN)
                Y[(size_t)r1 * 64 + (col >> 1)] =
                    __floats2half2_rn(acc[mi][ni][2] + b0, acc[mi][ni][3] + b1);
        }
    }
}

// ---------------- CSR build (batched over 3 matrices) ----------------
__global__ void hist3_kernel(const int* __restrict__ r0, const int* __restrict__ r1,
                             const int* __restrict__ r2) {
    const int* rows = (blockIdx.y == 0) ? r0 : (blockIdx.y == 1) ? r1 : r2;
    int* cnt = g_cnt[blockIdx.y];
    int i = (blockIdx.x * blockDim.x + threadIdx.x) * 4;
    if (i + 3 < EE) {
        int4 r = __ldg((const int4*)(rows + i));
        atomicAdd(&cnt[r.x], 1); atomicAdd(&cnt[r.y], 1);
        atomicAdd(&cnt[r.z], 1); atomicAdd(&cnt[r.w], 1);
    } else {
        for (int j = i; j < EE; j++) atomicAdd(&cnt[rows[j]], 1);
    }
}

__global__ void csr_part_kernel() {
    __shared__ int sh[SCHUNK];
    int m = blockIdx.y;
    int i = blockIdx.x * SCHUNK + threadIdx.x;
    sh[threadIdx.x] = (i < NN) ? g_cnt[m][i] : 0;
    __syncthreads();
    for (int off = SCHUNK / 2; off > 0; off >>= 1) {
        if (threadIdx.x < off) sh[threadIdx.x] += sh[threadIdx.x + off];
        __syncthreads();
    }
    if (threadIdx.x == 0) g_bsum[m][blockIdx.x] = sh[0];
}

__global__ void csr_scanpart_kernel() {
    __shared__ int sh[512];
    int m = blockIdx.x;
    int t = threadIdx.x;
    int v = (t < SNB) ? g_bsum[m][t] : 0;
    sh[t] = v;
    __syncthreads();
    for (int off = 1; off < 512; off <<= 1) {
        int u = 0;
        if (t >= off) u = sh[t - off];
        __syncthreads();
        if (t >= off) sh[t] += u;
        __syncthreads();
    }
    if (t < SNB) g_boff[m][t] = sh[t] - v;
    if (t == 511) g_rowptr[m][NN] = sh[511];
}

__global__ void csr_fin_kernel() {
    __shared__ int sh[SCHUNK];
    int m = blockIdx.y;
    int t = threadIdx.x;
    int i = blockIdx.x * SCHUNK + t;
    int c = (i < NN) ? g_cnt[m][i] : 0;
    sh[t] = c;
    __syncthreads();
    for (int off = 1; off < SCHUNK; off <<= 1) {
        int u = 0;
        if (t >= off) u = sh[t - off];
        __syncthreads();
        if (t >= off) sh[t] += u;
        __syncthreads();
    }
    if (i < NN) {
        int excl = sh[t] - c + g_boff[m][blockIdx.x];
        g_rowptr[m][i] = excl;
        g_cursor[m][i] = excl;
        g_cnt[m][i] = 0;
    }
}

__global__ void scatter3_kernel(const int* __restrict__ r0, const int* __restrict__ r1,
                                const int* __restrict__ r2,
                                const int* __restrict__ c0, const int* __restrict__ c1,
                                const int* __restrict__ c2,
                                const float* __restrict__ v0, const float* __restrict__ v1,
                                const float* __restrict__ v2) {
    int m = blockIdx.y;
    const int* rows = (m == 0) ? r0 : (m == 1) ? r1 : r2;
    const int* cols = (m == 0) ? c0 : (m == 1) ? c1 : c2;
    const float* vals = (m == 0) ? v0 : (m == 1) ? v1 : v2;
    int i = blockIdx.x * blockDim.x + threadIdx.x;
    if (i < EE) {
        int r = rows[i];
        int p = atomicAdd(&g_cursor[m][r], 1);
        g_epack[m][p] = make_int2(cols[i], __float_as_int(vals[i]));
    }
}

// ---------------- SpMM: warp per row, fp16 gather, MLP-4, fp32 accumulate ----------
__global__ void spmm_kernel(const int* __restrict__ rowptr, const int2* __restrict__ ep,
                            const uint2* __restrict__ x,
                            float* __restrict__ yF, uint2* __restrict__ yH,
                            float* __restrict__ acc, int relu, int accWrite) {
    int gwarp = (blockIdx.x * blockDim.x + threadIdx.x) >> 5;
    int lane  = threadIdx.x & 31;
    if (gwarp >= NN) return;
    int e = rowptr[gwarp];
    int end = rowptr[gwarp + 1];

    float4 s0 = make_float4(0.f, 0.f, 0.f, 0.f);
    float4 s1 = make_float4(0.f, 0.f, 0.f, 0.f);
    for (; e + 3 < end; e += 4) {
        int2 p0 = __ldg(&ep[e]);
        int2 p1 = __ldg(&ep[e + 1]);
        int2 p2 = __ldg(&ep[e + 2]);
        int2 p3 = __ldg(&ep[e + 3]);
        uint2 r0 = __ldg(&x[(size_t)p0.x * 32 + lane]);
        uint2 r1 = __ldg(&x[(size_t)p1.x * 32 + lane]);
        uint2 r2 = __ldg(&x[(size_t)p2.x * 32 + lane]);
        uint2 r3 = __ldg(&x[(size_t)p3.x * 32 + lane]);
        float v0 = __int_as_float(p0.y), v1 = __int_as_float(p1.y);
        float v2 = __int_as_float(p2.y), v3 = __int_as_float(p3.y);
        float2 a0 = __half22float2(*(__half2*)&r0.x), a1 = __half22float2(*(__half2*)&r0.y);
        float2 b0 = __half22float2(*(__half2*)&r1.x), b1 = __half22float2(*(__half2*)&r1.y);
        float2 c0 = __half22float2(*(__half2*)&r2.x), c1 = __half22float2(*(__half2*)&r2.y);
        float2 d0 = __half22float2(*(__half2*)&r3.x), d1 = __half22float2(*(__half2*)&r3.y);
        s0.x += v0 * a0.x + v1 * b0.x; s0.y += v0 * a0.y + v1 * b0.y;
        s0.z += v0 * a1.x + v1 * b1.x; s0.w += v0 * a1.y + v1 * b1.y;
        s1.x += v2 * c0.x + v3 * d0.x; s1.y += v2 * c0.y + v3 * d0.y;
        s1.z += v2 * c1.x + v3 * d1.x; s1.w += v2 * c1.y + v3 * d1.y;
    }
    for (; e < end; e++) {
        int2 p0 = __ldg(&ep[e]);
        float v0 = __int_as_float(p0.y);
        uint2 r0 = __ldg(&x[(size_t)p0.x * 32 + lane]);
        float2 a0 = __half22float2(*(__half2*)&r0.x), a1 = __half22float2(*(__half2*)&r0.y);
        s0.x += v0 * a0.x; s0.y += v0 * a0.y; s0.z += v0 * a1.x; s0.w += v0 * a1.y;
    }
    float4 r;
    r.x = s0.x + s1.x; r.y = s0.y + s1.y; r.z = s0.z + s1.z; r.w = s0.w + s1.w;
    if (relu) {
        r.x = fmaxf(r.x, 0.f); r.y = fmaxf(r.y, 0.f);
        r.z = fmaxf(r.z, 0.f); r.w = fmaxf(r.w, 0.f);
    }
    size_t oi = (size_t)gwarp * 32 + lane;
    if (yF) ((float4*)yF)[oi] = r;
    if (yH) {
        __half2 h0 = __floats2half2_rn(r.x, r.y);
        __half2 h1 = __floats2half2_rn(r.z, r.w);
        uint2 hv;
        hv.x = *(unsigned*)&h0; hv.y = *(unsigned*)&h1;
        yH[oi] = hv;
    }
    if (acc) {
        if (accWrite) {
            ((float4*)acc)[oi] = r;
        } else {
            float4 o = ((float4*)acc)[oi];
            o.x += r.x; o.y += r.y; o.z += r.z; o.w += r.w;
            ((float4*)acc)[oi] = o;
        }
    }
}

// ---------------- Gated fusion: warp handles 4 nodes, both views; fp16 out ----------
__global__ void fusion_kernel(const float* __restrict__ x, const float* __restrict__ W1,
                              const float* __restrict__ b1, const float* __restrict__ w2,
                              const float* __restrict__ b2, uint2* __restrict__ fusedH) {
    float* sm = (float*)dynsm;
    float* Ws = sm;                 // 128*128
    float* Xs = sm + DD * DD;       // 32 nodes * 2 views * 128
    __shared__ float b1s[DD];
    __shared__ float w2s[DD];

    const float4* W4 = (const float4*)W1;
    float4* Ws4 = (float4*)Ws;
    for (int i = threadIdx.x; i < DD * DD / 4; i += blockDim.x) Ws4[i] = W4[i];
    if (threadIdx.x < DD) {
        b1s[threadIdx.x] = b1[threadIdx.x];
        w2s[threadIdx.x] = w2[threadIdx.x];
    }
    const float b2v = b2[0];

    const int nodeBase = blockIdx.x * 32;
    const float4* x4 = (const float4*)x;
    float4* Xs4 = (float4*)Xs;
    for (int i = threadIdx.x; i < 32 * 2 * 32; i += blockDim.x) {
        int node = i >> 6;
        int v    = (i >> 5) & 1;
        int q    = i & 31;
        int gn   = nodeBase + node;
        Xs4[i] = (gn < NN) ? __ldg(&x4[((size_t)v * NN + gn) * 32 + q])
                           : make_float4(0.f, 0.f, 0.f, 0.f);
    }
    __syncthreads();

    const int warp = threadIdx.x >> 5;
    const int lane = threadIdx.x & 31;
    const int n0 = warp * 4;

    float sc[2][4];
#pragma unroll
    for (int v = 0; v < 2; v++) {
        float4 acc[4];
#pragma unroll
        for (int r = 0; r < 4; r++) acc[r] = make_float4(0.f, 0.f, 0.f, 0.f);
#pragma unroll 2
        for (int k = 0; k < DD; k++) {
            float4 wv = *(const float4*)(Ws + k * DD + lane * 4);
#pragma unroll
            for (int r = 0; r < 4; r++) {
                float xk = Xs[((n0 + r) * 2 + v) * DD + k];
                acc[r].x += xk * wv.x;
                acc[r].y += xk * wv.y;
                acc[r].z += xk * wv.z;
                acc[r].w += xk * wv.w;
            }
        }
#pragma unroll
        for (int r = 0; r < 4; r++) {
            float h0 = tanhf(acc[r].x + b1s[lane * 4 + 0]);
            float h1 = tanhf(acc[r].y + b1s[lane * 4 + 1]);
            float h2 = tanhf(acc[r].z + b1s[lane * 4 + 2]);
            float h3 = tanhf(acc[r].w + b1s[lane * 4 + 3]);
            float p = h0 * w2s[lane * 4 + 0] + h1 * w2s[lane * 4 + 1] +
                      h2 * w2s[lane * 4 + 2] + h3 * w2s[lane * 4 + 3];
#pragma unroll
            for (int off = 16; off > 0; off >>= 1)
                p += __shfl_xor_sync(0xffffffffu, p, off);
            sc[v][r] = p + b2v;
        }
    }

#pragma unroll
    for (int r = 0; r < 4; r++) {
        int node = nodeBase + n0 + r;
        if (node >= NN) continue;
        float m  = fmaxf(sc[0][r], sc[1][r]);
        float e0 = expf(sc[0][r] - m);
        float e1 = expf(sc[1][r] - m);
        float inv = 1.f / (e0 + e1);
        float s0 = e0 * inv, s1 = e1 * inv;
        float4 a = Xs4[((n0 + r) * 2 + 0) * 32 + lane];
        float4 b = Xs4[((n0 + r) * 2 + 1) * 32 + lane];
        __half2 h0 = __floats2half2_rn(s0 * a.x + s1 * b.x, s0 * a.y + s1 * b.y);
        __half2 h1 = __floats2half2_rn(s0 * a.z + s1 * b.z, s0 * a.w + s1 * b.w);
        uint2 hv;
        hv.x = *(unsigned*)&h0; hv.y = *(unsigned*)&h1;
        fusedH[(size_t)node * 32 + lane] = hv;
    }
}

// ---------------- host ----------------
extern "C" void kernel_launch(void* const* d_in, const int* in_sizes, int n_in,
                              void* d_out, int out_size) {
    const float* x    = (const float*)d_in[0];
    const float* fw1  = (const float*)d_in[1];
    const float* fb1  = (const float*)d_in[2];
    const float* fw2  = (const float*)d_in[3];
    const float* fb2  = (const float*)d_in[4];
    const float* hgw  = (const float*)d_in[5];
    const float* lgw  = (const float*)d_in[6];
    const float* lgb  = (const float*)d_in[7];
    const float* c1v  = (const float*)d_in[8];
    const float* c2v  = (const float*)d_in[9];
    const float* lgv  = (const float*)d_in[10];
    const int* c1r = (const int*)d_in[11];
    const int* c1c = (const int*)d_in[12];
    const int* c2r = (const int*)d_in[13];
    const int* c2c = (const int*)d_in[14];
    const int* lgr = (const int*)d_in[15];
    const int* lgc = (const int*)d_in[16];
    float* out  = (float*)d_out;              // [2N, D]
    float* out2 = out + (size_t)NN * DD;

    __half2 *h16a, *h16b;
    int *rowptrBase;
    int2 *epackBase;
    __half *wtBase;
    cudaGetSymbolAddress((void**)&h16a, g_h16a);
    cudaGetSymbolAddress((void**)&h16b, g_h16b);
    cudaGetSymbolAddress((void**)&rowptrBase, g_rowptr);
    cudaGetSymbolAddress((void**)&epackBase, g_epack);
    cudaGetSymbolAddress((void**)&wtBase, g_wt);

    int* rowptr[3];
    int2* epack[3];
    for (int m = 0; m < 3; m++) {
        rowptr[m] = rowptrBase + (size_t)m * (NN + 1);
        epack[m]  = epackBase + (size_t)m * EE;
    }
    const uint4* wt[5];
    for (int m = 0; m < 5; m++) wt[m] = (const uint4*)(wtBase + (size_t)m * DD * DD);

    const size_t smemFusion = (size_t)(DD * DD + 64 * DD) * sizeof(float);        // 96 KB
    const size_t smemMMA = 2 * 128 * AST * sizeof(__half) + DD * sizeof(float);   // ~70 KB
    cudaFuncSetAttribute(fusion_kernel, cudaFuncAttributeMaxDynamicSharedMemorySize, (int)smemFusion);
    cudaFuncSetAttribute(mma_linear_kernel, cudaFuncAttributeMaxDynamicSharedMemorySize, (int)smemMMA);

    const int SPB = (NN * 32 + 255) / 256;   // spmm warp-per-row grid
    const int FB  = (NN + 31) / 32;          // fusion grid
    const int MB  = (NN + 127) / 128;        // mma tile grid (782)

    // ---- weight prep ----
    wprep_kernel<<<dim3(64, 5), 256>>>(hgw, lgw);

    // ---- CSR builds (batched) ----
    hist3_kernel<<<dim3(3125, 3), 256>>>(c1r, c2r, lgr);
    csr_part_kernel<<<dim3(SNB, 3), SCHUNK>>>();
    csr_scanpart_kernel<<<3, 512>>>();
    csr_fin_kernel<<<dim3(SNB, 3), SCHUNK>>>();
    scatter3_kernel<<<dim3((EE + 255) / 256, 3), 256>>>(c1r, c2r, lgr, c1c, c2c, lgc,
                                                        c1v, c2v, lgv);

    // ---- gated fusion -> h16b (fp16) ----
    fusion_kernel<<<FB, 256, smemFusion>>>(x, fw1, fb1, fw2, fb2, (uint2*)h16b);

    // ---- HypergraphConv ----
    mma_linear_kernel<<<MB, 256, smemMMA>>>((const uint4*)h16b, wt[0], nullptr, h16a);
    spmm_kernel<<<SPB, 256>>>(rowptr[0], epack[0], (const uint2*)h16a, nullptr, (uint2*)h16b, nullptr, 1, 0);
    mma_linear_kernel<<<MB, 256, smemMMA>>>((const uint4*)h16b, wt[1], nullptr, h16a);
    spmm_kernel<<<SPB, 256>>>(rowptr[0], epack[0], (const uint2*)h16a, nullptr, (uint2*)h16b, nullptr, 1, 0);
    mma_linear_kernel<<<MB, 256, smemMMA>>>((const uint4*)h16b, wt[2], nullptr, h16a);
    // h -> out (fp32) + fp16 shadow h16b
    spmm_kernel<<<SPB, 256>>>(rowptr[0], epack[0], (const uint2*)h16a, out, (uint2*)h16b, nullptr, 1, 0);
    // y = relu(spmm(coef2, h)) -> h16a (fp16) + out2 (acc init)
    spmm_kernel<<<SPB, 256>>>(rowptr[1], epack[1], (const uint2*)h16b, nullptr, (uint2*)h16a, out2, 1, 1);

    // ---- LineConv ----
    mma_linear_kernel<<<MB, 256, smemMMA>>>((const uint4*)h16a, wt[3], lgb, h16b);
    spmm_kernel<<<SPB, 256>>>(rowptr[2], epack[2], (const uint2*)h16b, nullptr, (uint2*)h16a, out2, 0, 0);
    mma_linear_kernel<<<MB, 256, smemMMA>>>((const uint4*)h16a, wt[4], lgb + DD, h16b);
    spmm_kernel<<<SPB, 256>>>(rowptr[2], epack[2], (const uint2*)h16b, nullptr, nullptr, out2, 0, 0);
}

// round 6
// speedup vs baseline: 2.4885x; 1.9060x over previous
#include <cuda_runtime.h>
#include <cuda_fp16.h>
#include <math.h>
#include <stdint.h>

#define NN 100000
#define DD 128
#define EE 3200000
#define SCHUNK 256
#define SNB ((NN + SCHUNK - 1) / SCHUNK)   // 391
#define AST 136                            // smem row stride (halves), conflict-free ldmatrix

extern __shared__ char dynsm[];

// ---------------- static device scratch ----------------
__device__ __half2 g_h16a[NN * (DD / 2)];
__device__ __half2 g_h16b[NN * (DD / 2)];
__device__ __half2 g_xh[2 * NN * (DD / 2)];
__device__ float  g_score[2 * NN];
__device__ int    g_cnt[3][NN];
__device__ int    g_cursor[3][NN];
__device__ int    g_rowptr[3][NN + 1];
__device__ int2   g_epack[3][EE];
__device__ int    g_bsum[3][SNB];
__device__ int    g_boff[3][SNB];
__device__ __half g_wt[6][DD * DD];        // transposed fp16 weights (5 linears + fusion_w1)

__device__ __forceinline__ uint32_t smem_u32(const void* p) {
    uint32_t a;
    asm("{ .reg .u64 t; cvta.to.shared.u64 t, %1; cvt.u32.u64 %0, t; }" : "=r"(a) : "l"(p));
    return a;
}

// ---------------- weight prep: fp16 transpose (6 matrices) ----------------
__global__ void wprep_kernel(const float* __restrict__ hgw, const float* __restrict__ lgw,
                             const float* __restrict__ fw1) {
    int m = blockIdx.y;
    const float* W = (m < 3) ? (hgw + (size_t)m * DD * DD)
                   : (m < 5) ? (lgw + (size_t)(m - 3) * DD * DD)
                             : fw1;
    int i = blockIdx.x * blockDim.x + threadIdx.x;
    if (i >= DD * DD) return;
    int n = i >> 7, k = i & 127;
    g_wt[m][n * DD + k] = __float2half_rn(__ldg(&W[k * DD + n]));
}

// ---------------- x fp32 -> fp16 (both views) ----------------
__global__ void xconv_kernel(const float4* __restrict__ x4, uint2* __restrict__ xh) {
    int i = blockIdx.x * blockDim.x + threadIdx.x;
    if (i < 2 * NN * 32) {
        float4 v = __ldg(&x4[i]);
        __half2 h0 = __floats2half2_rn(v.x, v.y);
        __half2 h1 = __floats2half2_rn(v.z, v.w);
        uint2 o;
        o.x = *(unsigned*)&h0; o.y = *(unsigned*)&h1;
        xh[i] = o;
    }
}

// ---------------- MMA linear: Y = half(X @ W + b); tile 128x128x128 ----------------
__global__ void __launch_bounds__(256, 2) mma_linear_kernel(
    const uint4* __restrict__ X, const uint4* __restrict__ Bt,
    const float* __restrict__ bias, __half2* __restrict__ Y)
{
    __half* sm = (__half*)dynsm;
    __half* sA = sm;
    __half* sB = sm + 128 * AST;
    float* bs = (float*)(sm + 2 * 128 * AST);

    const int tid = threadIdx.x;
    const int lane = tid & 31;
    const int warp = tid >> 5;
    const int warpM = warp & 3;
    const int warpN = warp >> 2;
    const int rowBase = blockIdx.x * 128;

    for (int i = tid; i < 2048; i += 256) {
        int r = i >> 4, c = i & 15;
        int gr = rowBase + r;
        uint4 v = (gr < NN) ? __ldg(&X[(size_t)gr * 16 + c]) : make_uint4(0u, 0u, 0u, 0u);
        *(uint4*)&sA[r * AST + c * 8] = v;
    }
    for (int i = tid; i < 2048; i += 256) {
        int r = i >> 4, c = i & 15;
        *(uint4*)&sB[r * AST + c * 8] = __ldg(&Bt[i]);
    }
    if (tid < 128) bs[tid] = bias ? __ldg(&bias[tid]) : 0.f;
    __syncthreads();

    float acc[2][8][4];
#pragma unroll
    for (int mi = 0; mi < 2; mi++)
#pragma unroll
        for (int ni = 0; ni < 8; ni++)
#pragma unroll
            for (int q = 0; q < 4; q++) acc[mi][ni][q] = 0.f;

#pragma unroll
    for (int k0 = 0; k0 < 128; k0 += 16) {
        uint32_t a[2][4];
#pragma unroll
        for (int mi = 0; mi < 2; mi++) {
            int row = warpM * 32 + mi * 16 + (lane & 15);
            int col = k0 + ((lane >> 4) << 3);
            uint32_t addr = smem_u32(&sA[row * AST + col]);
            asm volatile("ldmatrix.sync.aligned.m8n8.x4.shared.b16 {%0,%1,%2,%3}, [%4];"
                         : "=r"(a[mi][0]), "=r"(a[mi][1]), "=r"(a[mi][2]), "=r"(a[mi][3])
                         : "r"(addr));
        }
        uint32_t b[8][2];
#pragma unroll
        for (int ni = 0; ni < 8; ni++) {
            int n = warpN * 64 + ni * 8 + (lane & 7);
            int col = k0 + (((lane >> 3) & 1) << 3);
            uint32_t addr = smem_u32(&sB[n * AST + col]);
            asm volatile("ldmatrix.sync.aligned.m8n8.x2.shared.b16 {%0,%1}, [%2];"
                         : "=r"(b[ni][0]), "=r"(b[ni][1]) : "r"(addr));
        }
#pragma unroll
        for (int mi = 0; mi < 2; mi++)
#pragma unroll
            for (int ni = 0; ni < 8; ni++) {
                asm volatile(
                    "mma.sync.aligned.m16n8k16.row.col.f32.f16.f16.f32 "
                    "{%0,%1,%2,%3}, {%4,%5,%6,%7}, {%8,%9}, {%0,%1,%2,%3};"
                    : "+f"(acc[mi][ni][0]), "+f"(acc[mi][ni][1]),
                      "+f"(acc[mi][ni][2]), "+f"(acc[mi][ni][3])
                    : "r"(a[mi][0]), "r"(a[mi][1]), "r"(a[mi][2]), "r"(a[mi][3]),
                      "r"(b[ni][0]), "r"(b[ni][1]));
            }
    }

    const int g = lane >> 2, t = lane & 3;
#pragma unroll
    for (int mi = 0; mi < 2; mi++) {
#pragma unroll
        for (int ni = 0; ni < 8; ni++) {
            int col = warpN * 64 + ni * 8 + t * 2;
            float b0 = bs[col], b1 = bs[col + 1];
            int r0 = rowBase + warpM * 32 + mi * 16 + g;
            int r1 = r0 + 8;
            if (r0 < NN)
                Y[(size_t)r0 * 64 + (col >> 1)] =
                    __floats2half2_rn(acc[mi][ni][0] + b0, acc[mi][ni][1] + b1);
            if (r1 < NN)
                Y[(size_t)r1 * 64 + (col >> 1)] =
                    __floats2half2_rn(acc[mi][ni][2] + b0, acc[mi][ni][3] + b1);
        }
    }
}

// ---------------- MMA score: p[r] = sum_c tanh((Xh@W1)[r,c] + b1[c]) * w2[c] ----------
__global__ void __launch_bounds__(256, 2) mma_score_kernel(
    const uint4* __restrict__ X,      // fp16 [2N,128]
    const uint4* __restrict__ Bt,     // fw1^T fp16
    const float* __restrict__ b1,
    const float* __restrict__ w2,
    float* __restrict__ score)        // [2N]
{
    __half* sm = (__half*)dynsm;
    __half* sA = sm;
    __half* sB = sm + 128 * AST;
    __shared__ float b1s[DD];
    __shared__ float w2s[DD];
    __shared__ float ssc[2][DD];

    const int tid = threadIdx.x;
    const int lane = tid & 31;
    const int warp = tid >> 5;
    const int warpM = warp & 3;
    const int warpN = warp >> 2;
    const int rowBase = blockIdx.x * 128;
    const int TOTR = 2 * NN;

    for (int i = tid; i < 2048; i += 256) {
        int r = i >> 4, c = i & 15;
        int gr = rowBase + r;
        uint4 v = (gr < TOTR) ? __ldg(&X[(size_t)gr * 16 + c]) : make_uint4(0u, 0u, 0u, 0u);
        *(uint4*)&sA[r * AST + c * 8] = v;
    }
    for (int i = tid; i < 2048; i += 256) {
        int r = i >> 4, c = i & 15;
        *(uint4*)&sB[r * AST + c * 8] = __ldg(&Bt[i]);
    }
    if (tid < 128) {
        b1s[tid] = __ldg(&b1[tid]);
        w2s[tid] = __ldg(&w2[tid]);
        ssc[0][tid] = 0.f;
        ssc[1][tid] = 0.f;
    }
    __syncthreads();

    float acc[2][8][4];
#pragma unroll
    for (int mi = 0; mi < 2; mi++)
#pragma unroll
        for (int ni = 0; ni < 8; ni++)
#pragma unroll
            for (int q = 0; q < 4; q++) acc[mi][ni][q] = 0.f;

#pragma unroll
    for (int k0 = 0; k0 < 128; k0 += 16) {
        uint32_t a[2][4];
#pragma unroll
        for (int mi = 0; mi < 2; mi++) {
            int row = warpM * 32 + mi * 16 + (lane & 15);
            int col = k0 + ((lane >> 4) << 3);
            uint32_t addr = smem_u32(&sA[row * AST + col]);
            asm volatile("ldmatrix.sync.aligned.m8n8.x4.shared.b16 {%0,%1,%2,%3}, [%4];"
                         : "=r"(a[mi][0]), "=r"(a[mi][1]), "=r"(a[mi][2]), "=r"(a[mi][3])
                         : "r"(addr));
        }
        uint32_t b[8][2];
#pragma unroll
        for (int ni = 0; ni < 8; ni++) {
            int n = warpN * 64 + ni * 8 + (lane & 7);
            int col = k0 + (((lane >> 3) & 1) << 3);
            uint32_t addr = smem_u32(&sB[n * AST + col]);
            asm volatile("ldmatrix.sync.aligned.m8n8.x2.shared.b16 {%0,%1}, [%2];"
                         : "=r"(b[ni][0]), "=r"(b[ni][1]) : "r"(addr));
        }
#pragma unroll
        for (int mi = 0; mi < 2; mi++)
#pragma unroll
            for (int ni = 0; ni < 8; ni++) {
                asm volatile(
                    "mma.sync.aligned.m16n8k16.row.col.f32.f16.f16.f32 "
                    "{%0,%1,%2,%3}, {%4,%5,%6,%7}, {%8,%9}, {%0,%1,%2,%3};"
                    : "+f"(acc[mi][ni][0]), "+f"(acc[mi][ni][1]),
                      "+f"(acc[mi][ni][2]), "+f"(acc[mi][ni][3])
                    : "r"(a[mi][0]), "r"(a[mi][1]), "r"(a[mi][2]), "r"(a[mi][3]),
                      "r"(b[ni][0]), "r"(b[ni][1]));
            }
    }

    const int g = lane >> 2, t = lane & 3;
#pragma unroll
    for (int mi = 0; mi < 2; mi++) {
        float pr0 = 0.f, pr1 = 0.f;
#pragma unroll
        for (int ni = 0; ni < 8; ni++) {
            int col = warpN * 64 + ni * 8 + t * 2;
            float w0 = w2s[col], w1 = w2s[col + 1];
            float c0 = b1s[col], c1 = b1s[col + 1];
            pr0 += tanhf(acc[mi][ni][0] + c0) * w0 + tanhf(acc[mi][ni][1] + c1) * w1;
            pr1 += tanhf(acc[mi][ni][2] + c0) * w0 + tanhf(acc[mi][ni][3] + c1) * w1;
        }
        pr0 += __shfl_xor_sync(0xffffffffu, pr0, 1);
        pr0 += __shfl_xor_sync(0xffffffffu, pr0, 2);
        pr1 += __shfl_xor_sync(0xffffffffu, pr1, 1);
        pr1 += __shfl_xor_sync(0xffffffffu, pr1, 2);
        if (t == 0) {
            ssc[warpN][warpM * 32 + mi * 16 + g] = pr0;
            ssc[warpN][warpM * 32 + mi * 16 + g + 8] = pr1;
        }
        // note: pr written per (warpN), rows distinct per writer
    }
    __syncthreads();
    if (tid < 128) {
        int gr = rowBase + tid;
        if (gr < TOTR) score[gr] = ssc[0][tid] + ssc[1][tid];
    }
}

// ---------------- gate: softmax over 2 scores, blend fp32 x -> fp16 fused ----------
__global__ void gate_kernel(const float4* __restrict__ x4, const float* __restrict__ score,
                            uint2* __restrict__ fused) {
    int gw = (blockIdx.x * blockDim.x + threadIdx.x) >> 5;
    int lane = threadIdx.x & 31;
    if (gw >= NN) return;
    float s0 = __ldg(&score[gw]);
    float s1 = __ldg(&score[gw + NN]);
    float m = fmaxf(s0, s1);
    float e0 = expf(s0 - m), e1 = expf(s1 - m);
    float inv = 1.f / (e0 + e1);
    float g0 = e0 * inv, g1 = e1 * inv;
    float4 a = __ldg(&x4[(size_t)gw * 32 + lane]);
    float4 b = __ldg(&x4[((size_t)NN + gw) * 32 + lane]);
    __half2 h0 = __floats2half2_rn(g0 * a.x + g1 * b.x, g0 * a.y + g1 * b.y);
    __half2 h1 = __floats2half2_rn(g0 * a.z + g1 * b.z, g0 * a.w + g1 * b.w);
    uint2 o;
    o.x = *(unsigned*)&h0; o.y = *(unsigned*)&h1;
    fused[(size_t)gw * 32 + lane] = o;
}

// ---------------- CSR build (batched over 3 matrices) ----------------
__global__ void hist3_kernel(const int* __restrict__ r0, const int* __restrict__ r1,
                             const int* __restrict__ r2) {
    const int* rows = (blockIdx.y == 0) ? r0 : (blockIdx.y == 1) ? r1 : r2;
    int* cnt = g_cnt[blockIdx.y];
    int i = (blockIdx.x * blockDim.x + threadIdx.x) * 4;
    if (i + 3 < EE) {
        int4 r = __ldg((const int4*)(rows + i));
        atomicAdd(&cnt[r.x], 1); atomicAdd(&cnt[r.y], 1);
        atomicAdd(&cnt[r.z], 1); atomicAdd(&cnt[r.w], 1);
    } else {
        for (int j = i; j < EE; j++) atomicAdd(&cnt[rows[j]], 1);
    }
}

__global__ void csr_part_kernel() {
    __shared__ int sh[SCHUNK];
    int m = blockIdx.y;
    int i = blockIdx.x * SCHUNK + threadIdx.x;
    sh[threadIdx.x] = (i < NN) ? g_cnt[m][i] : 0;
    __syncthreads();
    for (int off = SCHUNK / 2; off > 0; off >>= 1) {
        if (threadIdx.x < off) sh[threadIdx.x] += sh[threadIdx.x + off];
        __syncthreads();
    }
    if (threadIdx.x == 0) g_bsum[m][blockIdx.x] = sh[0];
}

__global__ void csr_scanpart_kernel() {
    __shared__ int sh[512];
    int m = blockIdx.x;
    int t = threadIdx.x;
    int v = (t < SNB) ? g_bsum[m][t] : 0;
    sh[t] = v;
    __syncthreads();
    for (int off = 1; off < 512; off <<= 1) {
        int u = 0;
        if (t >= off) u = sh[t - off];
        __syncthreads();
        if (t >= off) sh[t] += u;
        __syncthreads();
    }
    if (t < SNB) g_boff[m][t] = sh[t] - v;
    if (t == 511) g_rowptr[m][NN] = sh[511];
}

__global__ void csr_fin_kernel() {
    __shared__ int sh[SCHUNK];
    int m = blockIdx.y;
    int t = threadIdx.x;
    int i = blockIdx.x * SCHUNK + t;
    int c = (i < NN) ? g_cnt[m][i] : 0;
    sh[t] = c;
    __syncthreads();
    for (int off = 1; off < SCHUNK; off <<= 1) {
        int u = 0;
        if (t >= off) u = sh[t - off];
        __syncthreads();
        if (t >= off) sh[t] += u;
        __syncthreads();
    }
    if (i < NN) {
        int excl = sh[t] - c + g_boff[m][blockIdx.x];
        g_rowptr[m][i] = excl;
        g_cursor[m][i] = excl;
        g_cnt[m][i] = 0;
    }
}

__global__ void scatter3_kernel(const int* __restrict__ r0, const int* __restrict__ r1,
                                const int* __restrict__ r2,
                                const int* __restrict__ c0, const int* __restrict__ c1,
                                const int* __restrict__ c2,
                                const float* __restrict__ v0, const float* __restrict__ v1,
                                const float* __restrict__ v2) {
    int m = blockIdx.y;
    const int* rows = (m == 0) ? r0 : (m == 1) ? r1 : r2;
    const int* cols = (m == 0) ? c0 : (m == 1) ? c1 : c2;
    const float* vals = (m == 0) ? v0 : (m == 1) ? v1 : v2;
    int i = blockIdx.x * blockDim.x + threadIdx.x;
    if (i < EE) {
        int r = rows[i];
        int p = atomicAdd(&g_cursor[m][r], 1);
        g_epack[m][p] = make_int2(cols[i], __float_as_int(vals[i]));
    }
}

// ---------------- SpMM: warp per row, 16 lanes x uint4 per row, 2 edges/warp-inst ----
__global__ void spmm_kernel(const int* __restrict__ rowptr, const int2* __restrict__ ep,
                            const uint4* __restrict__ x,
                            float* __restrict__ yF, uint2* __restrict__ yH,
                            float* __restrict__ acc, int relu, int accWrite) {
    int gwarp = (blockIdx.x * blockDim.x + threadIdx.x) >> 5;
    int lane  = threadIdx.x & 31;
    int hr = lane >> 4;        // 0 or 1: which edge of the pair
    int li = lane & 15;        // 16B chunk within row
    int beg = rowptr[gwarp];
    int end = rowptr[gwarp + 1];

    float a8[8];
#pragma unroll
    for (int k = 0; k < 8; k++) a8[k] = 0.f;

    int e = beg;
    for (; e + 3 < end; e += 4) {
        int2 p0 = __ldg(&ep[e + hr]);
        int2 p1 = __ldg(&ep[e + 2 + hr]);
        uint4 v0 = __ldg(&x[(size_t)p0.x * 16 + li]);
        uint4 v1 = __ldg(&x[(size_t)p1.x * 16 + li]);
        float w0 = __int_as_float(p0.y), w1 = __int_as_float(p1.y);
        float2 f0 = __half22float2(*(__half2*)&v0.x);
        float2 f1 = __half22float2(*(__half2*)&v0.y);
        float2 f2 = __half22float2(*(__half2*)&v0.z);
        float2 f3 = __half22float2(*(__half2*)&v0.w);
        a8[0] += w0 * f0.x; a8[1] += w0 * f0.y; a8[2] += w0 * f1.x; a8[3] += w0 * f1.y;
        a8[4] += w0 * f2.x; a8[5] += w0 * f2.y; a8[6] += w0 * f3.x; a8[7] += w0 * f3.y;
        f0 = __half22float2(*(__half2*)&v1.x);
        f1 = __half22float2(*(__half2*)&v1.y);
        f2 = __half22float2(*(__half2*)&v1.z);
        f3 = __half22float2(*(__half2*)&v1.w);
        a8[0] += w1 * f0.x; a8[1] += w1 * f0.y; a8[2] += w1 * f1.x; a8[3] += w1 * f1.y;
        a8[4] += w1 * f2.x; a8[5] += w1 * f2.y; a8[6] += w1 * f3.x; a8[7] += w1 * f3.y;
    }
    for (; e + 1 < end; e += 2) {
        int2 p0 = __ldg(&ep[e + hr]);
        uint4 v0 = __ldg(&x[(size_t)p0.x * 16 + li]);
        float w0 = __int_as_float(p0.y);
        float2 f0 = __half22float2(*(__half2*)&v0.x);
        float2 f1 = __half22float2(*(__half2*)&v0.y);
        float2 f2 = __half22float2(*(__half2*)&v0.z);
        float2 f3 = __half22float2(*(__half2*)&v0.w);
        a8[0] += w0 * f0.x; a8[1] += w0 * f0.y; a8[2] += w0 * f1.x; a8[3] += w0 * f1.y;
        a8[4] += w0 * f2.x; a8[5] += w0 * f2.y; a8[6] += w0 * f3.x; a8[7] += w0 * f3.y;
    }
    if (e < end && hr == 0) {
        int2 p0 = __ldg(&ep[e]);
        uint4 v0 = __ldg(&x[(size_t)p0.x * 16 + li]);
        float w0 = __int_as_float(p0.y);
        float2 f0 = __half22float2(*(__half2*)&v0.x);
        float2 f1 = __half22float2(*(__half2*)&v0.y);
        float2 f2 = __half22float2(*(__half2*)&v0.z);
        float2 f3 = __half22float2(*(__half2*)&v0.w);
        a8[0] += w0 * f0.x; a8[1] += w0 * f0.y; a8[2] += w0 * f1.x; a8[3] += w0 * f1.y;
        a8[4] += w0 * f2.x; a8[5] += w0 * f2.y; a8[6] += w0 * f3.x; a8[7] += w0 * f3.y;
    }

    // combine the two half-warps (lane l and l+16 hold same columns)
#pragma unroll
    for (int k = 0; k < 8; k++) a8[k] += __shfl_xor_sync(0xffffffffu, a8[k], 16);

    float4 r;
    r.x = a8[hr * 4 + 0]; r.y = a8[hr * 4 + 1];
    r.z = a8[hr * 4 + 2]; r.w = a8[hr * 4 + 3];
    if (relu) {
        r.x = fmaxf(r.x, 0.f); r.y = fmaxf(r.y, 0.f);
        r.z = fmaxf(r.z, 0.f); r.w = fmaxf(r.w, 0.f);
    }
    size_t oi = (size_t)gwarp * 32 + li * 2 + hr;
    if (yF) ((float4*)yF)[oi] = r;
    if (yH) {
        __half2 h0 = __floats2half2_rn(r.x, r.y);
        __half2 h1 = __floats2half2_rn(r.z, r.w);
        uint2 hv;
        hv.x = *(unsigned*)&h0; hv.y = *(unsigned*)&h1;
        yH[oi] = hv;
    }
    if (acc) {
        if (accWrite) {
            ((float4*)acc)[oi] = r;
        } else {
            float4 o = ((float4*)acc)[oi];
            o.x += r.x; o.y += r.y; o.z += r.z; o.w += r.w;
            ((float4*)acc)[oi] = o;
        }
    }
}

// ---------------- host ----------------
extern "C" void kernel_launch(void* const* d_in, const int* in_sizes, int n_in,
                              void* d_out, int out_size) {
    const float* x    = (const float*)d_in[0];
    const float* fw1  = (const float*)d_in[1];
    const float* fb1  = (const float*)d_in[2];
    const float* fw2  = (const float*)d_in[3];
    const float* fb2  = (const float*)d_in[4];
    const float* hgw  = (const float*)d_in[5];
    const float* lgw  = (const float*)d_in[6];
    const float* lgb  = (const float*)d_in[7];
    const float* c1v  = (const float*)d_in[8];
    const float* c2v  = (const float*)d_in[9];
    const float* lgv  = (const float*)d_in[10];
    const int* c1r = (const int*)d_in[11];
    const int* c1c = (const int*)d_in[12];
    const int* c2r = (const int*)d_in[13];
    const int* c2c = (const int*)d_in[14];
    const int* lgr = (const int*)d_in[15];
    const int* lgc = (const int*)d_in[16];
    float* out  = (float*)d_out;              // [2N, D]
    float* out2 = out + (size_t)NN * DD;
    (void)fb2;                                 // softmax-invariant

    __half2 *h16a, *h16b, *xh;
    float* score;
    int *rowptrBase;
    int2 *epackBase;
    __half *wtBase;
    cudaGetSymbolAddress((void**)&h16a, g_h16a);
    cudaGetSymbolAddress((void**)&h16b, g_h16b);
    cudaGetSymbolAddress((void**)&xh, g_xh);
    cudaGetSymbolAddress((void**)&score, g_score);
    cudaGetSymbolAddress((void**)&rowptrBase, g_rowptr);
    cudaGetSymbolAddress((void**)&epackBase, g_epack);
    cudaGetSymbolAddress((void**)&wtBase, g_wt);

    int* rowptr[3];
    int2* epack[3];
    for (int m = 0; m < 3; m++) {
        rowptr[m] = rowptrBase + (size_t)m * (NN + 1);
        epack[m]  = epackBase + (size_t)m * EE;
    }
    const uint4* wt[6];
    for (int m = 0; m < 6; m++) wt[m] = (const uint4*)(wtBase + (size_t)m * DD * DD);

    const size_t smemMMA = 2 * 128 * AST * sizeof(__half) + DD * sizeof(float);   // ~70 KB
    cudaFuncSetAttribute(mma_linear_kernel, cudaFuncAttributeMaxDynamicSharedMemorySize, (int)smemMMA);
    cudaFuncSetAttribute(mma_score_kernel, cudaFuncAttributeMaxDynamicSharedMemorySize, (int)smemMMA);

    const int SPB = (NN * 32 + 255) / 256;    // spmm warp-per-row grid
    const int MB  = (NN + 127) / 128;         // mma tile grid (782)
    const int MB2 = (2 * NN + 127) / 128;     // score grid (1563)

    // ---- weight prep + x fp16 conversion ----
    wprep_kernel<<<dim3(64, 6), 256>>>(hgw, lgw, fw1);
    xconv_kernel<<<(2 * NN * 32 + 255) / 256, 256>>>((const float4*)x, (uint2*)xh);

    // ---- CSR builds (batched) ----
    hist3_kernel<<<dim3(3125, 3), 256>>>(c1r, c2r, lgr);
    csr_part_kernel<<<dim3(SNB, 3), SCHUNK>>>();
    csr_scanpart_kernel<<<3, 512>>>();
    csr_fin_kernel<<<dim3(SNB, 3), SCHUNK>>>();
    scatter3_kernel<<<dim3((EE + 255) / 256, 3), 256>>>(c1r, c2r, lgr, c1c, c2c, lgc,
                                                        c1v, c2v, lgv);

    // ---- gated fusion: score GEMM (fp16 tensor core) + softmax gate -> h16b ----
    mma_score_kernel<<<MB2, 256, smemMMA>>>((const uint4*)xh, wt[5], fb1, fw2, score);
    gate_kernel<<<SPB, 256>>>((const float4*)x, score, (uint2*)h16b);

    // ---- HypergraphConv ----
    mma_linear_kernel<<<MB, 256, smemMMA>>>((const uint4*)h16b, wt[0], nullptr, h16a);
    spmm_kernel<<<SPB, 256>>>(rowptr[0], epack[0], (const uint4*)h16a, nullptr, (uint2*)h16b, nullptr, 1, 0);
    mma_linear_kernel<<<MB, 256, smemMMA>>>((const uint4*)h16b, wt[1], nullptr, h16a);
    spmm_kernel<<<SPB, 256>>>(rowptr[0], epack[0], (const uint4*)h16a, nullptr, (uint2*)h16b, nullptr, 1, 0);
    mma_linear_kernel<<<MB, 256, smemMMA>>>((const uint4*)h16b, wt[2], nullptr, h16a);
    // h -> out (fp32) + fp16 shadow h16b
    spmm_kernel<<<SPB, 256>>>(rowptr[0], epack[0], (const uint4*)h16a, out, (uint2*)h16b, nullptr, 1, 0);
    // y = relu(spmm(coef2, h)) -> h16a (fp16) + out2 (acc init)
    spmm_kernel<<<SPB, 256>>>(rowptr[1], epack[1], (const uint4*)h16b, nullptr, (uint2*)h16a, out2, 1, 1);

    // ---- LineConv ----
    mma_linear_kernel<<<MB, 256, smemMMA>>>((const uint4*)h16a, wt[3], lgb, h16b);
    spmm_kernel<<<SPB, 256>>>(rowptr[2], epack[2], (const uint4*)h16b, nullptr, (uint2*)h16a, out2, 0, 0);
    mma_linear_kernel<<<MB, 256, smemMMA>>>((const uint4*)h16a, wt[4], lgb + DD, h16b);
    spmm_kernel<<<SPB, 256>>>(rowptr[2], epack[2], (const uint4*)h16b, nullptr, nullptr, out2, 0, 0);
}